// round 5
// baseline (speedup 1.0000x reference)
#include <cuda_runtime.h>
#include <cstdint>

// Conv2d: x[3,2048,2048] fp32 * k[16,3,3,3] fp32, pad=1, stride=1 -> out[16,2048,2048]
//
// R4: direct conv with sm_103a fma.rn.f32x2 (FFMA2).
//   - grid (8, 256, 2): block = 8 rows x 256 cols x 8 output channels.
//   - thread = 8 px (two 4-px groups at cols 4tx and 4tx+128) x 8 oc = 64 outputs,
//     held as 32 packed f32x2 accumulators (64 regs).
//   - weights packed (w,w) u64 in smem, loaded as ulonglong2 -> 108 LDS.128/thread
//     (was 432 LDS.64 in R3). 864 FFMA2/thread unchanged.
//   - all smem accesses at 16B thread stride: bank-conflict-free.

#define HW    2048
#define PLANE (2048 * 2048)

typedef unsigned long long u64;

__device__ __forceinline__ u64 pack2(float a, float b) {
    u64 r;
    asm("mov.b64 %0, {%1, %2};"
        : "=l"(r) : "r"(__float_as_uint(a)), "r"(__float_as_uint(b)));
    return r;
}

__device__ __forceinline__ void ffma2(u64& d, u64 a, u64 b) {
    asm("fma.rn.f32x2 %0, %1, %2, %0;" : "+l"(d) : "l"(a), "l"(b));
}

__device__ __forceinline__ float2 unpack2(u64 v) {
    unsigned lo, hi;
    asm("mov.b64 {%0, %1}, %2;" : "=r"(lo), "=r"(hi) : "l"(v));
    return make_float2(__uint_as_float(lo), __uint_as_float(hi));
}

__global__ __launch_bounds__(256, 2)
void conv3x3_f32x2_v2_kernel(const float* __restrict__ x,
                             const float* __restrict__ kern,
                             float* __restrict__ out) {
    // Input tile: 3 ch, 8+2 rows, 256+2 cols (padded to 264 -> 1056B rows, 16B-aligned).
    __shared__ __align__(16) float s_in[3][10][264];
    // Weights for this block's 8 OC: (w,w) u64, layout [tap][oc], tap = ic*9+kh*3+kw.
    __shared__ __align__(16) u64 s_w[27 * 8];

    const int tid  = threadIdx.x;
    const int bx   = blockIdx.x;      // 8 tiles of 256 cols
    const int by   = blockIdx.y;      // 256 tiles of 8 rows
    const int ocg  = blockIdx.z;      // 2 groups of 8 OC
    const int row0 = by * 8 - 1;
    const int col0 = bx * 256 - 1;

    // ---- Stage weights (216 values) ----
    if (tid < 216) {
        int oc = tid / 27;
        int t  = tid - oc * 27;       // ic*9 + kh*3 + kw
        unsigned u = __float_as_uint(kern[(ocg * 8 + oc) * 27 + t]);
        s_w[t * 8 + oc] = ((u64)u << 32) | u;
    }

    // ---- Stage input tile with zero padding: 3 x 10 x 258 ----
    #pragma unroll
    for (int ic = 0; ic < 3; ++ic) {
        const float* xp = x + ic * PLANE;
        #pragma unroll
        for (int r = 0; r < 10; ++r) {
            int gy = row0 + r;
            bool rowok = (unsigned)gy < (unsigned)HW;
            const float* rowp = xp + gy * HW;
            for (int c = tid; c < 258; c += 256) {
                int gx = col0 + c;
                float v = 0.0f;
                if (rowok && (unsigned)gx < (unsigned)HW) v = rowp[gx];
                s_in[ic][r][c] = v;
            }
        }
    }
    __syncthreads();

    const int tx = tid & 31;          // 32 threads across W
    const int ty = tid >> 5;          // 8 rows

    // acc[oc*4 + g*2 + p]: g = pixel group (cols 4tx / 4tx+128), p = pixel pair
    u64 acc[32];
    #pragma unroll
    for (int i = 0; i < 32; ++i) acc[i] = 0ull;

    #pragma unroll
    for (int ic = 0; ic < 3; ++ic) {
        #pragma unroll
        for (int kh = 0; kh < 3; ++kh) {
            const float* rp = &s_in[ic][ty + kh][tx * 4];
            // Group 0: cols tx*4 .. tx*4+5
            float4 a4 = *reinterpret_cast<const float4*>(rp);
            float2 a2 = *reinterpret_cast<const float2*>(rp + 4);
            // Group 1: cols tx*4+128 .. +133
            float4 b4 = *reinterpret_cast<const float4*>(rp + 128);
            float2 b2 = *reinterpret_cast<const float2*>(rp + 132);

            u64 A01 = pack2(a4.x, a4.y), A23 = pack2(a4.z, a4.w);
            u64 A12 = pack2(a4.y, a4.z), A34 = pack2(a4.w, a2.x);
            u64 A45 = pack2(a2.x, a2.y);
            u64 B01 = pack2(b4.x, b4.y), B23 = pack2(b4.z, b4.w);
            u64 B12 = pack2(b4.y, b4.z), B34 = pack2(b4.w, b2.x);
            u64 B45 = pack2(b2.x, b2.y);

            const int tap0 = (ic * 9 + kh * 3) * 8;

            // kw = 0: pairs (A01,A23) / (B01,B23)
            {
                const ulonglong2* wp = reinterpret_cast<const ulonglong2*>(&s_w[tap0]);
                #pragma unroll
                for (int o2 = 0; o2 < 4; ++o2) {
                    ulonglong2 w = wp[o2];
                    int b = (2 * o2) * 4;
                    ffma2(acc[b + 0], A01, w.x); ffma2(acc[b + 1], A23, w.x);
                    ffma2(acc[b + 2], B01, w.x); ffma2(acc[b + 3], B23, w.x);
                    ffma2(acc[b + 4], A01, w.y); ffma2(acc[b + 5], A23, w.y);
                    ffma2(acc[b + 6], B01, w.y); ffma2(acc[b + 7], B23, w.y);
                }
            }
            // kw = 1: pairs (A12,A34) / (B12,B34)
            {
                const ulonglong2* wp = reinterpret_cast<const ulonglong2*>(&s_w[tap0 + 8]);
                #pragma unroll
                for (int o2 = 0; o2 < 4; ++o2) {
                    ulonglong2 w = wp[o2];
                    int b = (2 * o2) * 4;
                    ffma2(acc[b + 0], A12, w.x); ffma2(acc[b + 1], A34, w.x);
                    ffma2(acc[b + 2], B12, w.x); ffma2(acc[b + 3], B34, w.x);
                    ffma2(acc[b + 4], A12, w.y); ffma2(acc[b + 5], A34, w.y);
                    ffma2(acc[b + 6], B12, w.y); ffma2(acc[b + 7], B34, w.y);
                }
            }
            // kw = 2: pairs (A23,A45) / (B23,B45)
            {
                const ulonglong2* wp = reinterpret_cast<const ulonglong2*>(&s_w[tap0 + 16]);
                #pragma unroll
                for (int o2 = 0; o2 < 4; ++o2) {
                    ulonglong2 w = wp[o2];
                    int b = (2 * o2) * 4;
                    ffma2(acc[b + 0], A23, w.x); ffma2(acc[b + 1], A45, w.x);
                    ffma2(acc[b + 2], B23, w.x); ffma2(acc[b + 3], B45, w.x);
                    ffma2(acc[b + 4], A23, w.y); ffma2(acc[b + 5], A45, w.y);
                    ffma2(acc[b + 6], B23, w.y); ffma2(acc[b + 7], B45, w.y);
                }
            }
        }
    }

    // ---- Epilogue: 8 oc x 2 groups of float4 coalesced stores ----
    const int orow = by * 8 + ty;
    const int ocol = bx * 256 + tx * 4;
    float* ob = out + (ocg * 8) * PLANE + orow * HW + ocol;
    #pragma unroll
    for (int oc = 0; oc < 8; ++oc) {
        float2 l0 = unpack2(acc[oc * 4 + 0]);
        float2 l1 = unpack2(acc[oc * 4 + 1]);
        float2 l2 = unpack2(acc[oc * 4 + 2]);
        float2 l3 = unpack2(acc[oc * 4 + 3]);
        float* p = ob + oc * PLANE;
        *reinterpret_cast<float4*>(p)       = make_float4(l0.x, l0.y, l1.x, l1.y);
        *reinterpret_cast<float4*>(p + 128) = make_float4(l2.x, l2.y, l3.x, l3.y);
    }
}

extern "C" void kernel_launch(void* const* d_in, const int* in_sizes, int n_in,
                              void* d_out, int out_size) {
    const float* x = (const float*)d_in[0];   // [3, 2048, 2048]
    const float* k = (const float*)d_in[1];   // [16, 3, 3, 3]
    float* out     = (float*)d_out;           // [16, 2048, 2048]

    dim3 grid(HW / 256, HW / 8, 2);           // (8, 256, 2)
    conv3x3_f32x2_v2_kernel<<<grid, 256>>>(x, k, out);
}

// round 6
// speedup vs baseline: 1.9856x; 1.9856x over previous
#include <cuda_runtime.h>
#include <cstdint>

// Conv2d: x[3,2048,2048] fp32 * k[16,3,3,3] fp32, pad=1, stride=1 -> out[16,2048,2048]
//
// R5: direct conv, sm_103a fma.rn.f32x2, occupancy-first.
//   - block = 512 threads: 32 tx (4 px each) x 8 ty (rows) x 2 oc-groups (8 OC each).
//     Tile = 8 rows x 128 cols x all 16 OC. Same DRAM traffic as R3.
//   - thread: 16 u64 accumulators (4 px x 8 oc) = 32 regs -> __launch_bounds__(512,2)
//     forces <=64 regs -> 2 CTAs x 16 warps = 32 warps/SM (2x R3's 16).
//   - weights: (w,w)-packed u64 in smem, warp-uniform ulonglong2 broadcast loads.
//     Per thread: 432 FFMA2, 108 LDS.128(w), 18 LDS(in), 45 packs.

#define HW    2048
#define PLANE (2048 * 2048)

typedef unsigned long long u64;

__device__ __forceinline__ u64 pack2(float a, float b) {
    u64 r;
    asm("mov.b64 %0, {%1, %2};"
        : "=l"(r) : "r"(__float_as_uint(a)), "r"(__float_as_uint(b)));
    return r;
}

__device__ __forceinline__ void ffma2(u64& d, u64 a, u64 b) {
    asm("fma.rn.f32x2 %0, %1, %2, %0;" : "+l"(d) : "l"(a), "l"(b));
}

__device__ __forceinline__ float2 unpack2(u64 v) {
    unsigned lo, hi;
    asm("mov.b64 {%0, %1}, %2;" : "=r"(lo), "=r"(hi) : "l"(v));
    return make_float2(__uint_as_float(lo), __uint_as_float(hi));
}

__global__ __launch_bounds__(512, 2)
void conv3x3_f32x2_v3_kernel(const float* __restrict__ x,
                             const float* __restrict__ kern,
                             float* __restrict__ out) {
    // Input tile: 3 ch, 8+2 rows, 128+2 cols padded to 132 (16B-aligned rows).
    __shared__ __align__(16) float s_in[3][10][132];
    // Weights (w,w)-packed, layout [tap][oc16], tap = ic*9 + kh*3 + kw.
    __shared__ __align__(16) u64 s_w[27 * 16];

    const int tid  = threadIdx.x;
    const int bx   = blockIdx.x;        // 16 tiles of 128 cols
    const int by   = blockIdx.y;        // 256 tiles of 8 rows
    const int row0 = by * 8 - 1;
    const int col0 = bx * 128 - 1;

    // ---- Stage weights: [oc][tap] -> [tap][oc], broadcast-packed (432 values) ----
    if (tid < 432) {
        int oc = tid / 27;
        int t  = tid - oc * 27;
        unsigned u = __float_as_uint(kern[tid]);
        s_w[t * 16 + oc] = ((u64)u << 32) | u;
    }

    // ---- Stage input tile with zero padding (3 * 10 * 130 = 3900 elems) ----
    for (int i = tid; i < 3900; i += 512) {
        int ic  = i / 1300;
        int rem = i - ic * 1300;
        int r   = rem / 130;
        int c   = rem - r * 130;
        int gy = row0 + r;
        int gx = col0 + c;
        float v = 0.0f;
        if ((unsigned)gy < (unsigned)HW && (unsigned)gx < (unsigned)HW)
            v = x[ic * PLANE + gy * HW + gx];
        s_in[ic][r][c] = v;
    }
    __syncthreads();

    const int tx = tid & 31;            // 32 threads across W (4 px each)
    const int ty = (tid >> 5) & 7;      // 8 rows
    const int og = tid >> 8;            // 2 oc-groups (uniform per warp)

    // acc[oc*2 + p]: oc = local output channel (0..7), p = pixel pair (0..1)
    u64 acc[16];
    #pragma unroll
    for (int i = 0; i < 16; ++i) acc[i] = 0ull;

    #pragma unroll
    for (int ic = 0; ic < 3; ++ic) {
        #pragma unroll
        for (int kh = 0; kh < 3; ++kh) {
            const float* rp = &s_in[ic][ty + kh][tx * 4];
            float4 v4 = *reinterpret_cast<const float4*>(rp);      // i0..i3
            float2 v2 = *reinterpret_cast<const float2*>(rp + 4);  // i4,i5
            u64 p01 = pack2(v4.x, v4.y), p23 = pack2(v4.z, v4.w);
            u64 p12 = pack2(v4.y, v4.z), p34 = pack2(v4.w, v2.x);
            u64 p45 = pack2(v2.x, v2.y);

            const int t0 = ic * 9 + kh * 3;
            const ulonglong2* w0 = reinterpret_cast<const ulonglong2*>(
                &s_w[(t0 + 0) * 16 + og * 8]);
            const ulonglong2* w1 = reinterpret_cast<const ulonglong2*>(
                &s_w[(t0 + 1) * 16 + og * 8]);
            const ulonglong2* w2 = reinterpret_cast<const ulonglong2*>(
                &s_w[(t0 + 2) * 16 + og * 8]);

            #pragma unroll
            for (int o2 = 0; o2 < 4; ++o2) {           // kw = 0: pairs (p01, p23)
                ulonglong2 w = w0[o2];
                ffma2(acc[4 * o2 + 0], p01, w.x); ffma2(acc[4 * o2 + 1], p23, w.x);
                ffma2(acc[4 * o2 + 2], p01, w.y); ffma2(acc[4 * o2 + 3], p23, w.y);
            }
            #pragma unroll
            for (int o2 = 0; o2 < 4; ++o2) {           // kw = 1: pairs (p12, p34)
                ulonglong2 w = w1[o2];
                ffma2(acc[4 * o2 + 0], p12, w.x); ffma2(acc[4 * o2 + 1], p34, w.x);
                ffma2(acc[4 * o2 + 2], p12, w.y); ffma2(acc[4 * o2 + 3], p34, w.y);
            }
            #pragma unroll
            for (int o2 = 0; o2 < 4; ++o2) {           // kw = 2: pairs (p23, p45)
                ulonglong2 w = w2[o2];
                ffma2(acc[4 * o2 + 0], p23, w.x); ffma2(acc[4 * o2 + 1], p45, w.x);
                ffma2(acc[4 * o2 + 2], p23, w.y); ffma2(acc[4 * o2 + 3], p45, w.y);
            }
        }
    }

    // ---- Epilogue: 8 oc x float4 coalesced stores ----
    const int orow = by * 8 + ty;
    const int ocol = bx * 128 + tx * 4;
    float* ob = out + (og * 8) * PLANE + orow * HW + ocol;
    #pragma unroll
    for (int oc = 0; oc < 8; ++oc) {
        float2 lo = unpack2(acc[oc * 2 + 0]);
        float2 hi = unpack2(acc[oc * 2 + 1]);
        *reinterpret_cast<float4*>(ob + oc * PLANE) =
            make_float4(lo.x, lo.y, hi.x, hi.y);
    }
}

extern "C" void kernel_launch(void* const* d_in, const int* in_sizes, int n_in,
                              void* d_out, int out_size) {
    const float* x = (const float*)d_in[0];   // [3, 2048, 2048]
    const float* k = (const float*)d_in[1];   // [16, 3, 3, 3]
    float* out     = (float*)d_out;           // [16, 2048, 2048]

    dim3 grid(HW / 128, HW / 8);              // (16, 256)
    conv3x3_f32x2_v3_kernel<<<grid, 512>>>(x, k, out);
}

// round 7
// speedup vs baseline: 2.0612x; 1.0380x over previous
#include <cuda_runtime.h>
#include <cstdint>

// Conv2d: x[3,2048,2048] fp32 * k[16,3,3,3] fp32, pad=1, stride=1 -> out[16,2048,2048]
//
// R6: direct conv, sm_103a fma.rn.f32x2, zero-pack main loop.
//   - block = 512 threads: 32 tx (4 px) x 8 ty (rows) x 2 oc-groups (8 OC).
//     Tile = 8 rows x 128 cols x 16 OC.
//   - input tile stored in smem PRE-PACKED as adjacent pairs: slot[c] = (v[c], v[c+1]),
//     laid out [c&3][c>>2] so the main-loop LDS.64 (thread stride 8B) is conflict-free.
//     All five shifted pairs per tap-row are direct LDS.64 -> no pack MOVs at all.
//   - weights (w,w)-packed u64 in smem, warp-uniform ulonglong2 loads.
//   - per thread main loop: 432 FFMA2, 108 LDS.128(w), 45 LDS.64(in), 0 packs.

#define HW    2048
#define PLANE (2048 * 2048)

typedef unsigned long long u64;

__device__ __forceinline__ void ffma2(u64& d, u64 a, u64 b) {
    asm("fma.rn.f32x2 %0, %1, %2, %0;" : "+l"(d) : "l"(a), "l"(b));
}

__device__ __forceinline__ float2 unpack2(u64 v) {
    unsigned lo, hi;
    asm("mov.b64 {%0, %1}, %2;" : "=r"(lo), "=r"(hi) : "l"(v));
    return make_float2(__uint_as_float(lo), __uint_as_float(hi));
}

__device__ __forceinline__ u64 lds_pair(const float2* p) {
    return *reinterpret_cast<const u64*>(p);
}

__global__ __launch_bounds__(512, 2)
void conv3x3_f32x2_v4_kernel(const float* __restrict__ x,
                             const float* __restrict__ kern,
                             float* __restrict__ out) {
    // Pair tile: slot s (s = 0..128) holds (v[s], v[s+1]) at [s&3][s>>2].
    // Dims: 3 ch x 10 rows x 4 x 34 slots (34 = 32 used + pad).
    __shared__ float2 s_pair[3][10][4][34];
    // Weights (w,w)-packed, layout [tap][oc16], tap = ic*9 + kh*3 + kw.
    __shared__ __align__(16) u64 s_w[27 * 16];

    const int tid  = threadIdx.x;
    const int bx   = blockIdx.x;        // 16 tiles of 128 cols
    const int by   = blockIdx.y;        // 256 tiles of 8 rows
    const int row0 = by * 8 - 1;
    const int col0 = bx * 128 - 1;

    // ---- Stage weights: [oc][tap] -> [tap][oc], broadcast-packed (432 values) ----
    if (tid < 432) {
        int oc = tid / 27;
        int t  = tid - oc * 27;
        unsigned u = __float_as_uint(kern[tid]);
        s_w[t * 16 + oc] = ((u64)u << 32) | u;
    }

    // ---- Stage input tile as adjacent pairs, zero-padded (3 * 10 * 130 values) ----
    for (int i = tid; i < 3900; i += 512) {
        int ic  = i / 1300;
        int rem = i - ic * 1300;
        int r   = rem / 130;
        int c   = rem - r * 130;        // 0..129
        int gy = row0 + r;
        int gx = col0 + c;
        float v = 0.0f;
        if ((unsigned)gy < (unsigned)HW && (unsigned)gx < (unsigned)HW)
            v = x[ic * PLANE + gy * HW + gx];
        // slot c gets .x = v[c]; slot c-1 gets .y = v[c]
        s_pair[ic][r][c & 3][c >> 2].x = v;
        if (c > 0)
            s_pair[ic][r][(c - 1) & 3][(c - 1) >> 2].y = v;
    }
    __syncthreads();

    const int tx = tid & 31;            // 32 threads across W (4 px each)
    const int ty = (tid >> 5) & 7;      // 8 rows
    const int og = tid >> 8;            // 2 oc-groups (uniform per warp)

    // acc[oc*2 + p]: oc = local output channel (0..7), p = pixel pair (0..1)
    u64 acc[16];
    #pragma unroll
    for (int i = 0; i < 16; ++i) acc[i] = 0ull;

    #pragma unroll
    for (int ic = 0; ic < 3; ++ic) {
        #pragma unroll
        for (int kh = 0; kh < 3; ++kh) {
            // Shifted pairs: slot 4tx+k = [k][tx] (k<4), slot 4tx+4 = [0][tx+1]
            const float2 (*row)[34] = s_pair[ic][ty + kh];
            u64 p01 = lds_pair(&row[0][tx]);
            u64 p12 = lds_pair(&row[1][tx]);
            u64 p23 = lds_pair(&row[2][tx]);
            u64 p34 = lds_pair(&row[3][tx]);
            u64 p45 = lds_pair(&row[0][tx + 1]);

            const int t0 = ic * 9 + kh * 3;
            const ulonglong2* w0 = reinterpret_cast<const ulonglong2*>(
                &s_w[(t0 + 0) * 16 + og * 8]);
            const ulonglong2* w1 = reinterpret_cast<const ulonglong2*>(
                &s_w[(t0 + 1) * 16 + og * 8]);
            const ulonglong2* w2 = reinterpret_cast<const ulonglong2*>(
                &s_w[(t0 + 2) * 16 + og * 8]);

            #pragma unroll
            for (int o2 = 0; o2 < 4; ++o2) {           // kw = 0: pairs (p01, p23)
                ulonglong2 w = w0[o2];
                ffma2(acc[4 * o2 + 0], p01, w.x); ffma2(acc[4 * o2 + 1], p23, w.x);
                ffma2(acc[4 * o2 + 2], p01, w.y); ffma2(acc[4 * o2 + 3], p23, w.y);
            }
            #pragma unroll
            for (int o2 = 0; o2 < 4; ++o2) {           // kw = 1: pairs (p12, p34)
                ulonglong2 w = w1[o2];
                ffma2(acc[4 * o2 + 0], p12, w.x); ffma2(acc[4 * o2 + 1], p34, w.x);
                ffma2(acc[4 * o2 + 2], p12, w.y); ffma2(acc[4 * o2 + 3], p34, w.y);
            }
            #pragma unroll
            for (int o2 = 0; o2 < 4; ++o2) {           // kw = 2: pairs (p23, p45)
                ulonglong2 w = w2[o2];
                ffma2(acc[4 * o2 + 0], p23, w.x); ffma2(acc[4 * o2 + 1], p45, w.x);
                ffma2(acc[4 * o2 + 2], p23, w.y); ffma2(acc[4 * o2 + 3], p45, w.y);
            }
        }
    }

    // ---- Epilogue: 8 oc x float4 coalesced stores ----
    const int orow = by * 8 + ty;
    const int ocol = bx * 128 + tx * 4;
    float* ob = out + (og * 8) * PLANE + orow * HW + ocol;
    #pragma unroll
    for (int oc = 0; oc < 8; ++oc) {
        float2 lo = unpack2(acc[oc * 2 + 0]);
        float2 hi = unpack2(acc[oc * 2 + 1]);
        *reinterpret_cast<float4*>(ob + oc * PLANE) =
            make_float4(lo.x, lo.y, hi.x, hi.y);
    }
}

extern "C" void kernel_launch(void* const* d_in, const int* in_sizes, int n_in,
                              void* d_out, int out_size) {
    const float* x = (const float*)d_in[0];   // [3, 2048, 2048]
    const float* k = (const float*)d_in[1];   // [16, 3, 3, 3]
    float* out     = (float*)d_out;           // [16, 2048, 2048]

    dim3 grid(HW / 128, HW / 8);              // (16, 256)
    conv3x3_f32x2_v4_kernel<<<grid, 512>>>(x, k, out);
}

// round 8
// speedup vs baseline: 2.3420x; 1.1363x over previous
#include <cuda_runtime.h>
#include <cstdint>

// Conv2d: x[3,2048,2048] fp32 * k[16,3,3,3] fp32, pad=1, stride=1 -> out[16,2048,2048]
//
// R7: direct conv, fma.rn.f32x2, FULL-occupancy version.
//   - block = 1024 threads: 32 tx (4 px) x 8 ty (rows) x 4 og (4 OC each).
//     Tile = 8 rows x 128 cols x 16 OC (same staging/DRAM as R6).
//   - thread: 8 u64 acc (4 px x 4 oc) = 16 regs; pair live-range managed so the
//     whole loop fits 32 regs -> __launch_bounds__(1024,2) -> 64 warps/SM (100% occ).
//   - input pre-paired in smem ([c&3][c>>2] layout, conflict-free LDS.64);
//     weights (w,w)-packed, warp-uniform broadcast ulonglong2 loads.

#define HW    2048
#define PLANE (2048 * 2048)

typedef unsigned long long u64;

__device__ __forceinline__ void ffma2(u64& d, u64 a, u64 b) {
    asm("fma.rn.f32x2 %0, %1, %2, %0;" : "+l"(d) : "l"(a), "l"(b));
}

__device__ __forceinline__ float2 unpack2(u64 v) {
    unsigned lo, hi;
    asm("mov.b64 {%0, %1}, %2;" : "=r"(lo), "=r"(hi) : "l"(v));
    return make_float2(__uint_as_float(lo), __uint_as_float(hi));
}

__device__ __forceinline__ u64 lds_pair(const float2* p) {
    return *reinterpret_cast<const u64*>(p);
}

__global__ __launch_bounds__(1024, 2)
void conv3x3_f32x2_v5_kernel(const float* __restrict__ x,
                             const float* __restrict__ kern,
                             float* __restrict__ out) {
    // Pair tile: slot s (0..128) holds (v[s], v[s+1]) at [s&3][s>>2].
    __shared__ float2 s_pair[3][10][4][34];
    // Weights (w,w)-packed, layout [tap][oc16], tap = ic*9 + kh*3 + kw.
    __shared__ __align__(16) u64 s_w[27 * 16];

    const int tid  = threadIdx.x;
    const int bx   = blockIdx.x;        // 16 tiles of 128 cols
    const int by   = blockIdx.y;        // 256 tiles of 8 rows
    const int row0 = by * 8 - 1;
    const int col0 = bx * 128 - 1;

    // ---- Stage weights (432 values) ----
    if (tid < 432) {
        int oc = tid / 27;
        int t  = tid - oc * 27;
        unsigned u = __float_as_uint(kern[tid]);
        s_w[t * 16 + oc] = ((u64)u << 32) | u;
    }

    // ---- Stage input tile as adjacent pairs, zero-padded (3 * 10 * 130 values) ----
    for (int i = tid; i < 3900; i += 1024) {
        int ic  = i / 1300;
        int rem = i - ic * 1300;
        int r   = rem / 130;
        int c   = rem - r * 130;        // 0..129
        int gy = row0 + r;
        int gx = col0 + c;
        float v = 0.0f;
        if ((unsigned)gy < (unsigned)HW && (unsigned)gx < (unsigned)HW)
            v = x[ic * PLANE + gy * HW + gx];
        s_pair[ic][r][c & 3][c >> 2].x = v;
        if (c > 0)
            s_pair[ic][r][(c - 1) & 3][(c - 1) >> 2].y = v;
    }
    __syncthreads();

    const int tx = tid & 31;            // 32 threads across W (4 px each)
    const int ty = (tid >> 5) & 7;      // 8 rows
    const int og = tid >> 8;            // 4 oc-groups of 4 OC (uniform per warp)

    // acc[oc*2 + p]: oc = local channel (0..3), p = pixel pair (0..1)
    u64 acc[8];
    #pragma unroll
    for (int i = 0; i < 8; ++i) acc[i] = 0ull;

    #pragma unroll
    for (int ic = 0; ic < 3; ++ic) {
        #pragma unroll
        for (int kh = 0; kh < 3; ++kh) {
            const float2 (*row)[34] = s_pair[ic][ty + kh];
            const int t0 = (ic * 9 + kh * 3) * 16 + og * 4;

            // kw = 0: pairs (p01, p23)
            u64 p01 = lds_pair(&row[0][tx]);
            u64 p23 = lds_pair(&row[2][tx]);
            {
                ulonglong2 wa = *reinterpret_cast<const ulonglong2*>(&s_w[t0]);
                ulonglong2 wb = *reinterpret_cast<const ulonglong2*>(&s_w[t0 + 2]);
                ffma2(acc[0], p01, wa.x); ffma2(acc[1], p23, wa.x);
                ffma2(acc[2], p01, wa.y); ffma2(acc[3], p23, wa.y);
                ffma2(acc[4], p01, wb.x); ffma2(acc[5], p23, wb.x);
                ffma2(acc[6], p01, wb.y); ffma2(acc[7], p23, wb.y);
            }
            // kw = 1: pairs (p12, p34)
            u64 p12 = lds_pair(&row[1][tx]);
            u64 p34 = lds_pair(&row[3][tx]);
            {
                ulonglong2 wa = *reinterpret_cast<const ulonglong2*>(&s_w[t0 + 16]);
                ulonglong2 wb = *reinterpret_cast<const ulonglong2*>(&s_w[t0 + 18]);
                ffma2(acc[0], p12, wa.x); ffma2(acc[1], p34, wa.x);
                ffma2(acc[2], p12, wa.y); ffma2(acc[3], p34, wa.y);
                ffma2(acc[4], p12, wb.x); ffma2(acc[5], p34, wb.x);
                ffma2(acc[6], p12, wb.y); ffma2(acc[7], p34, wb.y);
            }
            // kw = 2: pairs (p23 held, p45)
            u64 p45 = lds_pair(&row[0][tx + 1]);
            {
                ulonglong2 wa = *reinterpret_cast<const ulonglong2*>(&s_w[t0 + 32]);
                ulonglong2 wb = *reinterpret_cast<const ulonglong2*>(&s_w[t0 + 34]);
                ffma2(acc[0], p23, wa.x); ffma2(acc[1], p45, wa.x);
                ffma2(acc[2], p23, wa.y); ffma2(acc[3], p45, wa.y);
                ffma2(acc[4], p23, wb.x); ffma2(acc[5], p45, wb.x);
                ffma2(acc[6], p23, wb.y); ffma2(acc[7], p45, wb.y);
            }
        }
    }

    // ---- Epilogue: 4 oc x float4 coalesced stores ----
    const int orow = by * 8 + ty;
    const int ocol = bx * 128 + tx * 4;
    float* ob = out + (og * 4) * PLANE + orow * HW + ocol;
    #pragma unroll
    for (int oc = 0; oc < 4; ++oc) {
        float2 lo = unpack2(acc[oc * 2 + 0]);
        float2 hi = unpack2(acc[oc * 2 + 1]);
        *reinterpret_cast<float4*>(ob + oc * PLANE) =
            make_float4(lo.x, lo.y, hi.x, hi.y);
    }
}

extern "C" void kernel_launch(void* const* d_in, const int* in_sizes, int n_in,
                              void* d_out, int out_size) {
    const float* x = (const float*)d_in[0];   // [3, 2048, 2048]
    const float* k = (const float*)d_in[1];   // [16, 3, 3, 3]
    float* out     = (float*)d_out;           // [16, 2048, 2048]

    dim3 grid(HW / 128, HW / 8);              // (16, 256)
    conv3x3_f32x2_v5_kernel<<<grid, 1024>>>(x, k, out);
}